// round 4
// baseline (speedup 1.0000x reference)
#include <cuda_runtime.h>
#include <cuda_fp16.h>
#include <cstdint>

#define B_  64
#define NI  2048
#define DI  16
#define NO  32
#define DO  32
#define CH  16            // i-chunks per (b) for round partials
#define IC  (NI / CH)     // 128 i per chunk

// Scratch (alloc-free rule: __device__ globals)
__device__ __half g_uhat[(size_t)B_ * NI * NO * DO];  // [b][i][o][d]  268 MB fp16
__device__ float  g_partA[B_ * CH * NO * DO];         // round0 partials
__device__ float  g_partB[B_ * CH * NO * DO];         // round1 partials
__device__ float  g_partC[B_ * CH * NO * DO];         // round2 partials

// ---------- packed f32x2 helpers (Blackwell FFMA2 via PTX) ----------
__device__ __forceinline__ unsigned long long splat2(float v) {
    unsigned long long r;
    asm("mov.b64 %0, {%1, %1};" : "=l"(r) : "f"(v));
    return r;
}
__device__ __forceinline__ unsigned long long pack2(float x, float y) {
    unsigned long long r;
    asm("mov.b64 %0, {%1, %2};" : "=l"(r) : "f"(x), "f"(y));
    return r;
}
__device__ __forceinline__ void ffma2(unsigned long long &d,
                                      unsigned long long a, unsigned long long b) {
    asm("fma.rn.f32x2 %0, %1, %2, %0;" : "+l"(d) : "l"(a), "l"(b));
}
__device__ __forceinline__ void add2(unsigned long long &d, unsigned long long a) {
    asm("add.rn.f32x2 %0, %0, %1;" : "+l"(d) : "l"(a));
}
__device__ __forceinline__ float2 unpack2(unsigned long long v) {
    float2 f;
    asm("mov.b64 {%0, %1}, %2;" : "=f"(f.x), "=f"(f.y) : "l"(v));
    return f;
}

// ---------------------------------------------------------------------------
// K1 (unchanged from R3): u_hat[b][i][o][d] = sum_k W[o][i][d][k] * x[b][i][k]
// ---------------------------------------------------------------------------
__global__ __launch_bounds__(512, 1)
void k1_uhat(const float* __restrict__ x, const float* __restrict__ W) {
    const int i = blockIdx.x;
    const int t = threadIdx.x;

    __shared__ __align__(16) float xs[DI][B_];   // [k][b], rows 256B
    {
        int idx = t;
        #pragma unroll
        for (int r = 0; r < 2; r++, idx += 512) {
            int b = idx >> 4, k = idx & 15;
            xs[k][b] = x[((size_t)b * NI + i) * DI + k];
        }
    }

    const int o = t >> 4, dp = t & 15;           // d = 2dp, 2dp+1
    const float4* wp = reinterpret_cast<const float4*>(W) +
                       ((((size_t)o * NI + i) * DO + 2 * dp) * DI >> 2);
    float4 qa = wp[0], qb = wp[1], qc = wp[2], qd = wp[3];   // W[o,i,2dp,0..15]
    float4 qe = wp[4], qf = wp[5], qg = wp[6], qh = wp[7];   // W[o,i,2dp+1,0..15]

    unsigned long long w0[16], w1[16];
    w0[0]=splat2(qa.x); w0[1]=splat2(qa.y); w0[2]=splat2(qa.z); w0[3]=splat2(qa.w);
    w0[4]=splat2(qb.x); w0[5]=splat2(qb.y); w0[6]=splat2(qb.z); w0[7]=splat2(qb.w);
    w0[8]=splat2(qc.x); w0[9]=splat2(qc.y); w0[10]=splat2(qc.z); w0[11]=splat2(qc.w);
    w0[12]=splat2(qd.x); w0[13]=splat2(qd.y); w0[14]=splat2(qd.z); w0[15]=splat2(qd.w);
    w1[0]=splat2(qe.x); w1[1]=splat2(qe.y); w1[2]=splat2(qe.z); w1[3]=splat2(qe.w);
    w1[4]=splat2(qf.x); w1[5]=splat2(qf.y); w1[6]=splat2(qf.z); w1[7]=splat2(qf.w);
    w1[8]=splat2(qg.x); w1[9]=splat2(qg.y); w1[10]=splat2(qg.z); w1[11]=splat2(qg.w);
    w1[12]=splat2(qh.x); w1[13]=splat2(qh.y); w1[14]=splat2(qh.z); w1[15]=splat2(qh.w);

    __syncthreads();

    __half2* ob = reinterpret_cast<__half2*>(g_uhat) +
                  (size_t)i * 512 + o * 16 + dp;
    const size_t bs2 = (size_t)NI * NO * DO / 2;   // half2 stride per b

    #pragma unroll 1
    for (int bq = 0; bq < 16; bq++) {
        const int b = bq * 4;
        unsigned long long a0p = 0ull, a0q = 0ull;   // d0: {b,b+1}, {b+2,b+3}
        unsigned long long a1p = 0ull, a1q = 0ull;   // d1
        #pragma unroll
        for (int k = 0; k < 16; k++) {
            ulonglong2 xq = *reinterpret_cast<const ulonglong2*>(&xs[k][b]);
            ffma2(a0p, w0[k], xq.x);
            ffma2(a0q, w0[k], xq.y);
            ffma2(a1p, w1[k], xq.x);
            ffma2(a1q, w1[k], xq.y);
        }
        float2 f0p = unpack2(a0p), f0q = unpack2(a0q);
        float2 f1p = unpack2(a1p), f1q = unpack2(a1q);
        ob[(size_t)(b + 0) * bs2] = __float22half2_rn(make_float2(f0p.x, f1p.x));
        ob[(size_t)(b + 1) * bs2] = __float22half2_rn(make_float2(f0p.y, f1p.y));
        ob[(size_t)(b + 2) * bs2] = __float22half2_rn(make_float2(f0q.x, f1q.x));
        ob[(size_t)(b + 3) * bs2] = __float22half2_rn(make_float2(f0q.y, f1q.y));
    }
}

// ---------------------------------------------------------------------------
// Routing round, fused vsum prologue, ping-pong prefetch, packed f32x2 phases.
// CTA = (chunk, b), 256 threads. Warp covers 8 o x 4 q (q owns 8 d).
// mode 0: uniform c=1/32, writes pA.
// mode 1: vsum = squash(reduce(pA)), writes pB.
// mode 2: vsum = squash(reduce(pA)) + squash(reduce(pB)), writes pC.
// ---------------------------------------------------------------------------
__global__ __launch_bounds__(256)
void k_round(int mode) {
    const int ch = blockIdx.x, b = blockIdx.y;
    const int t = threadIdx.x;
    const int w = t >> 5, lane = t & 31;
    const int o = ((w & 3) << 3) + (lane >> 2);
    const int q = lane & 3;                 // owns d = 8q .. 8q+7
    const int half = w >> 2;                // i-subgroup within batch

    // ---- prologue: recompute vsum for this thread's (o, 8 d) from partials
    unsigned long long vs2[4];
    if (mode >= 1) {
        float vsum[8];
        #pragma unroll
        for (int d = 0; d < 8; d++) vsum[d] = 0.f;

        const float* bufs[2] = { g_partA, g_partB };
        const int nbuf = (mode == 2) ? 2 : 1;
        for (int bi = 0; bi < nbuf; bi++) {
            float s0[8];
            #pragma unroll
            for (int d = 0; d < 8; d++) s0[d] = 0.f;
            const float4* pp = reinterpret_cast<const float4*>(
                bufs[bi] + (size_t)(b * CH) * (NO * DO) + o * DO + q * 8);
            #pragma unroll
            for (int c = 0; c < CH; c++) {
                float4 x0 = pp[c * (NO * DO / 4)];
                float4 x1 = pp[c * (NO * DO / 4) + 1];
                s0[0]+=x0.x; s0[1]+=x0.y; s0[2]+=x0.z; s0[3]+=x0.w;
                s0[4]+=x1.x; s0[5]+=x1.y; s0[6]+=x1.z; s0[7]+=x1.w;
            }
            float nrm = 0.f;
            #pragma unroll
            for (int d = 0; d < 8; d++) nrm += s0[d] * s0[d];
            nrm += __shfl_xor_sync(0xffffffffu, nrm, 1);
            nrm += __shfl_xor_sync(0xffffffffu, nrm, 2);   // full ||s||^2 over 32 d
            float scale = nrm / (1.0f + nrm) * rsqrtf(nrm + 1e-7f);
            #pragma unroll
            for (int d = 0; d < 8; d++) vsum[d] += s0[d] * scale;
        }
        #pragma unroll
        for (int p = 0; p < 4; p++) vs2[p] = pack2(vsum[2*p], vsum[2*p+1]);
    }

    unsigned long long sp2[4] = {0ull, 0ull, 0ull, 0ull};

    __shared__ float s_db[8][NO];
    __shared__ float s_c[8][NO];

    // uint4 = 8 halves; 128 uint4 per i
    const uint4* up = reinterpret_cast<const uint4*>(g_uhat) +
                      ((size_t)b * NI + (size_t)ch * IC) * 128 + o * 4 + q;

    auto body = [&](uint4* raw, int /*unused*/) {
        // convert to packed float2 pairs (kept live across barriers)
        unsigned long long F2[4][4];
        #pragma unroll
        for (int v = 0; v < 4; v++) {
            const unsigned* ru = reinterpret_cast<const unsigned*>(&raw[v]);
            #pragma unroll
            for (int p = 0; p < 4; p++) {
                __half2 h = *reinterpret_cast<const __half2*>(&ru[p]);
                float2 f = __half22float2(h);
                F2[v][p] = pack2(f.x, f.y);
            }
        }
        if (mode >= 1) {
            // phase A: db = vsum . u_hat (packed dot, reduce over 4 q-lanes)
            #pragma unroll
            for (int v = 0; v < 4; v++) {
                unsigned long long acc = 0ull;
                #pragma unroll
                for (int p = 0; p < 4; p++) ffma2(acc, F2[v][p], vs2[p]);
                float2 a = unpack2(acc);
                float db = a.x + a.y;
                db += __shfl_xor_sync(0xffffffffu, db, 2);
                db += __shfl_xor_sync(0xffffffffu, db, 1);
                if (q == 0) s_db[half * 4 + v][o] = db;
            }
            __syncthreads();
            // phase B: softmax over o; warp w handles i_local = w, lane = o
            {
                float db = s_db[w][lane];
                float m = db;
                #pragma unroll
                for (int st = 16; st; st >>= 1)
                    m = fmaxf(m, __shfl_xor_sync(0xffffffffu, m, st));
                float e = __expf(db - m);
                float sm = e;
                #pragma unroll
                for (int st = 16; st; st >>= 1)
                    sm += __shfl_xor_sync(0xffffffffu, sm, st);
                s_c[w][lane] = __fdividef(e, sm);
            }
            __syncthreads();
            // phase C: s += c * u_hat (packed)
            #pragma unroll
            for (int v = 0; v < 4; v++) {
                unsigned long long c2 = splat2(s_c[half * 4 + v][o]);
                #pragma unroll
                for (int p = 0; p < 4; p++) ffma2(sp2[p], c2, F2[v][p]);
            }
        } else {
            #pragma unroll
            for (int v = 0; v < 4; v++)
                #pragma unroll
                for (int p = 0; p < 4; p++) add2(sp2[p], F2[v][p]);
        }
    };

    // ping-pong prefetch: batches of 8 i, two in flight
    uint4 rA[4], rB[4];
    #pragma unroll
    for (int v = 0; v < 4; v++)
        rA[v] = up[(size_t)(half * 4 + v) * 128];

    #pragma unroll 1
    for (int ib = 0; ib < IC; ib += 16) {
        #pragma unroll
        for (int v = 0; v < 4; v++)
            rB[v] = up[(size_t)(ib + 8 + half * 4 + v) * 128];
        body(rA, ib);
        if (ib + 16 < IC) {
            #pragma unroll
            for (int v = 0; v < 4; v++)
                rA[v] = up[(size_t)(ib + 16 + half * 4 + v) * 128];
        }
        body(rB, ib + 8);
    }

    float sp[8];
    {
        float2 f0 = unpack2(sp2[0]), f1 = unpack2(sp2[1]);
        float2 f2 = unpack2(sp2[2]), f3 = unpack2(sp2[3]);
        sp[0]=f0.x; sp[1]=f0.y; sp[2]=f1.x; sp[3]=f1.y;
        sp[4]=f2.x; sp[5]=f2.y; sp[6]=f3.x; sp[7]=f3.y;
    }
    if (mode == 0) {
        const float c = 1.0f / (float)NO;
        #pragma unroll
        for (int d = 0; d < 8; d++) sp[d] *= c;
    }

    // combine the two i-half-groups, write partials
    __shared__ float s_red[256 * 8];
    #pragma unroll
    for (int d = 0; d < 8; d++)
        s_red[(t & 127) * 8 + d + (half ? 1024 : 0)] = sp[d];
    __syncthreads();
    if (half == 0) {
        float* wb = (mode == 0) ? g_partA : (mode == 1 ? g_partB : g_partC);
        float4* pp = reinterpret_cast<float4*>(
            wb + ((b * CH + ch) * (NO * DO)) + o * DO + q * 8);
        int base = (t & 127) * 8;
        float4 r0, r1;
        r0.x = s_red[base+0] + s_red[base+0+1024];
        r0.y = s_red[base+1] + s_red[base+1+1024];
        r0.z = s_red[base+2] + s_red[base+2+1024];
        r0.w = s_red[base+3] + s_red[base+3+1024];
        r1.x = s_red[base+4] + s_red[base+4+1024];
        r1.y = s_red[base+5] + s_red[base+5+1024];
        r1.z = s_red[base+6] + s_red[base+6+1024];
        r1.w = s_red[base+7] + s_red[base+7+1024];
        pp[0] = r0; pp[1] = r1;
    }
}

// ---------------------------------------------------------------------------
// Final: reduce round-2 partials -> s, squash -> v, write output.
// Block per b, 1024 threads: warp = o, lane = d.
// ---------------------------------------------------------------------------
__global__ __launch_bounds__(1024)
void k_fin(float* __restrict__ out) {
    const int b = blockIdx.x, t = threadIdx.x;
    float s = 0.f;
    #pragma unroll
    for (int c = 0; c < CH; c++)
        s += g_partC[(b * CH + c) * (NO * DO) + t];

    float sq = s * s;
    #pragma unroll
    for (int st = 16; st; st >>= 1)
        sq += __shfl_xor_sync(0xffffffffu, sq, st);   // ||s||^2 over d

    float scale = sq / (1.0f + sq) * rsqrtf(sq + 1e-7f);
    out[b * (NO * DO) + t] = s * scale;
}

// ---------------------------------------------------------------------------
extern "C" void kernel_launch(void* const* d_in, const int* in_sizes, int n_in,
                              void* d_out, int out_size) {
    const float* x = (const float*)d_in[0];
    const float* W = (const float*)d_in[1];
    if (in_sizes[0] != B_ * NI * DI) {   // robust to metadata ordering
        x = (const float*)d_in[1];
        W = (const float*)d_in[0];
    }
    float* out = (float*)d_out;

    k1_uhat<<<NI, 512>>>(x, W);

    dim3 rg(CH, B_);
    k_round<<<rg, 256>>>(0);
    k_round<<<rg, 256>>>(1);
    k_round<<<rg, 256>>>(2);
    k_fin<<<B_, NO * DO>>>(out);
}

// round 5
// speedup vs baseline: 1.0213x; 1.0213x over previous
#include <cuda_runtime.h>
#include <cuda_fp16.h>
#include <cstdint>

#define B_  64
#define NI  2048
#define DI  16
#define NO  32
#define DO  32
#define CH  16            // i-chunks per (b) for round partials
#define IC  (NI / CH)     // 128 i per chunk

// u_hat layout: [b][i][p(4)][o(32)][8 halves]  (p = d8 chunk). 268 MB fp16.
__device__ __half g_uhat[(size_t)B_ * NI * NO * DO];
__device__ float  g_partA[B_ * CH * NO * DO];         // round0 partials
__device__ float  g_partB[B_ * CH * NO * DO];         // round1 partials
__device__ float  g_partC[B_ * CH * NO * DO];         // round2 partials

// ---------- packed f32x2 helpers (Blackwell FFMA2 via PTX) ----------
__device__ __forceinline__ unsigned long long splat2(float v) {
    unsigned long long r;
    asm("mov.b64 %0, {%1, %1};" : "=l"(r) : "f"(v));
    return r;
}
__device__ __forceinline__ unsigned long long pack2(float x, float y) {
    unsigned long long r;
    asm("mov.b64 %0, {%1, %2};" : "=l"(r) : "f"(x), "f"(y));
    return r;
}
__device__ __forceinline__ void ffma2(unsigned long long &d,
                                      unsigned long long a, unsigned long long b) {
    asm("fma.rn.f32x2 %0, %1, %2, %0;" : "+l"(d) : "l"(a), "l"(b));
}
__device__ __forceinline__ void add2(unsigned long long &d, unsigned long long a) {
    asm("add.rn.f32x2 %0, %0, %1;" : "+l"(d) : "l"(a));
}
__device__ __forceinline__ float2 unpack2(unsigned long long v) {
    float2 f;
    asm("mov.b64 {%0, %1}, %2;" : "=f"(f.x), "=f"(f.y) : "l"(v));
    return f;
}

// ---------------------------------------------------------------------------
// K1: u_hat[b][i][o][d] = sum_k W[o][i][d][k] * x[b][i][k]  (fp16, permuted)
// CTA per i, 512 threads; thread owns (o, dp) -> d = 2dp, 2dp+1.
// Output half2 slot: i*512 + (dp>>2)*128 + o*4 + (dp&3).
// ---------------------------------------------------------------------------
__global__ __launch_bounds__(512, 1)
void k1_uhat(const float* __restrict__ x, const float* __restrict__ W) {
    const int i = blockIdx.x;
    const int t = threadIdx.x;

    __shared__ __align__(16) float xs[DI][B_];   // [k][b], rows 256B
    {
        int idx = t;
        #pragma unroll
        for (int r = 0; r < 2; r++, idx += 512) {
            int b = idx >> 4, k = idx & 15;
            xs[k][b] = x[((size_t)b * NI + i) * DI + k];
        }
    }

    const int o = t >> 4, dp = t & 15;           // d = 2dp, 2dp+1
    const float4* wp = reinterpret_cast<const float4*>(W) +
                       ((((size_t)o * NI + i) * DO + 2 * dp) * DI >> 2);
    float4 qa = wp[0], qb = wp[1], qc = wp[2], qd = wp[3];   // W[o,i,2dp,0..15]
    float4 qe = wp[4], qf = wp[5], qg = wp[6], qh = wp[7];   // W[o,i,2dp+1,0..15]

    unsigned long long w0[16], w1[16];
    w0[0]=splat2(qa.x); w0[1]=splat2(qa.y); w0[2]=splat2(qa.z); w0[3]=splat2(qa.w);
    w0[4]=splat2(qb.x); w0[5]=splat2(qb.y); w0[6]=splat2(qb.z); w0[7]=splat2(qb.w);
    w0[8]=splat2(qc.x); w0[9]=splat2(qc.y); w0[10]=splat2(qc.z); w0[11]=splat2(qc.w);
    w0[12]=splat2(qd.x); w0[13]=splat2(qd.y); w0[14]=splat2(qd.z); w0[15]=splat2(qd.w);
    w1[0]=splat2(qe.x); w1[1]=splat2(qe.y); w1[2]=splat2(qe.z); w1[3]=splat2(qe.w);
    w1[4]=splat2(qf.x); w1[5]=splat2(qf.y); w1[6]=splat2(qf.z); w1[7]=splat2(qf.w);
    w1[8]=splat2(qg.x); w1[9]=splat2(qg.y); w1[10]=splat2(qg.z); w1[11]=splat2(qg.w);
    w1[12]=splat2(qh.x); w1[13]=splat2(qh.y); w1[14]=splat2(qh.z); w1[15]=splat2(qh.w);

    __syncthreads();

    // permuted output slot
    __half2* ob = reinterpret_cast<__half2*>(g_uhat) +
                  (size_t)i * 512 + (dp >> 2) * 128 + o * 4 + (dp & 3);
    const size_t bs2 = (size_t)NI * 512;          // half2 stride per b

    #pragma unroll 1
    for (int bq = 0; bq < 16; bq++) {
        const int b = bq * 4;
        unsigned long long a0p = 0ull, a0q = 0ull;   // d0: {b,b+1}, {b+2,b+3}
        unsigned long long a1p = 0ull, a1q = 0ull;   // d1
        #pragma unroll
        for (int k = 0; k < 16; k++) {
            ulonglong2 xq = *reinterpret_cast<const ulonglong2*>(&xs[k][b]);
            ffma2(a0p, w0[k], xq.x);
            ffma2(a0q, w0[k], xq.y);
            ffma2(a1p, w1[k], xq.x);
            ffma2(a1q, w1[k], xq.y);
        }
        float2 f0p = unpack2(a0p), f0q = unpack2(a0q);
        float2 f1p = unpack2(a1p), f1q = unpack2(a1q);
        ob[(size_t)(b + 0) * bs2] = __float22half2_rn(make_float2(f0p.x, f1p.x));
        ob[(size_t)(b + 1) * bs2] = __float22half2_rn(make_float2(f0p.y, f1p.y));
        ob[(size_t)(b + 2) * bs2] = __float22half2_rn(make_float2(f0q.x, f1q.x));
        ob[(size_t)(b + 3) * bs2] = __float22half2_rn(make_float2(f0q.y, f1q.y));
    }
}

// ---------------------------------------------------------------------------
// Routing round, barrier-free mainloop. CTA = (chunk, b), 256 threads, 8 warps.
// Warp handles 16 i; lane = o owns the full 32-d vector of (o, i).
// Softmax over o = warp shuffle reduce. Fused vsum prologue from partials.
// mode 0: uniform c=1/32 -> pA.  mode 1: v(pA) -> pB.  mode 2: v(pA)+v(pB) -> pC.
// ---------------------------------------------------------------------------
__global__ __launch_bounds__(256, 2)
void k_round(int mode) {
    const int ch = blockIdx.x, b = blockIdx.y;
    const int t = threadIdx.x;
    const int w = t >> 5, lane = t & 31;

    __shared__ float sv[NO * 33];          // padded vsum [o][d]
    __shared__ float s_red[8][34 * NO];    // per-warp s partials, padded

    // ---- prologue: vsum -> smem (cooperative, coalesced), then regs per-lane
    unsigned long long vs2[16];
    if (mode >= 1) {
        const int po = t >> 3, pq = t & 7;          // po = o, pq owns 4 d
        float vsum[4] = {0.f, 0.f, 0.f, 0.f};
        const float* bufs[2] = { g_partA, g_partB };
        const int nbuf = (mode == 2) ? 2 : 1;
        for (int bi = 0; bi < nbuf; bi++) {
            float s0[4] = {0.f, 0.f, 0.f, 0.f};
            const float4* pp = reinterpret_cast<const float4*>(
                bufs[bi] + (size_t)(b * CH) * (NO * DO)) + t;
            #pragma unroll
            for (int c = 0; c < CH; c++) {
                float4 v4 = pp[c * (NO * DO / 4)];
                s0[0]+=v4.x; s0[1]+=v4.y; s0[2]+=v4.z; s0[3]+=v4.w;
            }
            float nrm = s0[0]*s0[0] + s0[1]*s0[1] + s0[2]*s0[2] + s0[3]*s0[3];
            nrm += __shfl_xor_sync(0xffffffffu, nrm, 1);
            nrm += __shfl_xor_sync(0xffffffffu, nrm, 2);
            nrm += __shfl_xor_sync(0xffffffffu, nrm, 4);   // ||s||^2 over 32 d
            float scale = nrm / (1.0f + nrm) * rsqrtf(nrm + 1e-7f);
            #pragma unroll
            for (int j = 0; j < 4; j++) vsum[j] += s0[j] * scale;
        }
        #pragma unroll
        for (int j = 0; j < 4; j++) sv[po * 33 + pq * 4 + j] = vsum[j];
        __syncthreads();
        #pragma unroll
        for (int k = 0; k < 16; k++)
            vs2[k] = pack2(sv[lane * 33 + 2*k], sv[lane * 33 + 2*k + 1]);
    }

    unsigned long long sp2[16];
    #pragma unroll
    for (int k = 0; k < 16; k++) sp2[k] = 0ull;

    // mainloop: warp w handles i = ch*IC + w*16 .. +15, lane = o
    const uint4* up = reinterpret_cast<const uint4*>(g_uhat) +
                      ((size_t)b * NI + (size_t)ch * IC + w * 16) * 128 + lane;
    const unsigned long long c132 = splat2(1.0f / (float)NO);

    uint4 cur[4], nxt[4];
    #pragma unroll
    for (int p = 0; p < 4; p++) cur[p] = up[p * 32];

    #pragma unroll 1
    for (int il = 0; il < 16; il++) {
        if (il < 15) {
            #pragma unroll
            for (int p = 0; p < 4; p++) nxt[p] = up[(il + 1) * 128 + p * 32];
        }
        // convert 32 halves -> 16 packed f32x2 (kept live through softmax)
        unsigned long long F2[16];
        #pragma unroll
        for (int p = 0; p < 4; p++) {
            const unsigned* ru = reinterpret_cast<const unsigned*>(&cur[p]);
            #pragma unroll
            for (int r = 0; r < 4; r++) {
                float2 f = __half22float2(*reinterpret_cast<const __half2*>(&ru[r]));
                F2[p * 4 + r] = pack2(f.x, f.y);
            }
        }
        if (mode >= 1) {
            // phase A: lane-private dot db = vsum[o,:] . u_hat[o,i,:]
            unsigned long long acc0 = 0ull, acc1 = 0ull;
            #pragma unroll
            for (int k = 0; k < 16; k++)
                ffma2((k & 1) ? acc1 : acc0, F2[k], vs2[k]);
            add2(acc0, acc1);
            float2 a = unpack2(acc0);
            float db = a.x + a.y;
            // phase B: warp softmax over o (lane = o), no smem / no barrier
            float m = db;
            #pragma unroll
            for (int st = 16; st; st >>= 1)
                m = fmaxf(m, __shfl_xor_sync(0xffffffffu, m, st));
            float e = __expf(db - m);
            float sm = e;
            #pragma unroll
            for (int st = 16; st; st >>= 1)
                sm += __shfl_xor_sync(0xffffffffu, sm, st);
            unsigned long long c2 = splat2(__fdividef(e, sm));
            // phase C: s[o,:] += c * u_hat[o,i,:]
            #pragma unroll
            for (int k = 0; k < 16; k++) ffma2(sp2[k], c2, F2[k]);
        } else {
            #pragma unroll
            for (int k = 0; k < 16; k++) ffma2(sp2[k], c132, F2[k]);
        }
        #pragma unroll
        for (int p = 0; p < 4; p++) cur[p] = nxt[p];
    }

    // combine 8 warps' partials via smem (single barrier), write g_part
    #pragma unroll
    for (int k = 0; k < 16; k++) {
        float2 f = unpack2(sp2[k]);
        s_red[w][lane * 34 + 2*k]     = f.x;
        s_red[w][lane * 34 + 2*k + 1] = f.y;
    }
    __syncthreads();
    {
        float* wb = (mode == 0) ? g_partA : (mode == 1 ? g_partB : g_partC);
        const int o = t >> 3, dq = (t & 7) * 4;      // 4 consecutive d
        float4 r;
        r.x = r.y = r.z = r.w = 0.f;
        #pragma unroll
        for (int ww = 0; ww < 8; ww++) {
            const float* sr = &s_red[ww][o * 34 + dq];
            r.x += sr[0]; r.y += sr[1]; r.z += sr[2]; r.w += sr[3];
        }
        reinterpret_cast<float4*>(
            wb + (size_t)(b * CH + ch) * (NO * DO))[t] = r;
    }
}

// ---------------------------------------------------------------------------
// Final: reduce round-2 partials -> s, squash -> v, write output.
// Block per b, 1024 threads: warp = o, lane = d.
// ---------------------------------------------------------------------------
__global__ __launch_bounds__(1024)
void k_fin(float* __restrict__ out) {
    const int b = blockIdx.x, t = threadIdx.x;
    float s = 0.f;
    #pragma unroll
    for (int c = 0; c < CH; c++)
        s += g_partC[(b * CH + c) * (NO * DO) + t];

    float sq = s * s;
    #pragma unroll
    for (int st = 16; st; st >>= 1)
        sq += __shfl_xor_sync(0xffffffffu, sq, st);   // ||s||^2 over d

    float scale = sq / (1.0f + sq) * rsqrtf(sq + 1e-7f);
    out[b * (NO * DO) + t] = s * scale;
}

// ---------------------------------------------------------------------------
extern "C" void kernel_launch(void* const* d_in, const int* in_sizes, int n_in,
                              void* d_out, int out_size) {
    const float* x = (const float*)d_in[0];
    const float* W = (const float*)d_in[1];
    if (in_sizes[0] != B_ * NI * DI) {   // robust to metadata ordering
        x = (const float*)d_in[1];
        W = (const float*)d_in[0];
    }
    float* out = (float*)d_out;

    k1_uhat<<<NI, 512>>>(x, W);

    dim3 rg(CH, B_);
    k_round<<<rg, 256>>>(0);
    k_round<<<rg, 256>>>(1);
    k_round<<<rg, 256>>>(2);
    k_fin<<<B_, NO * DO>>>(out);
}

// round 6
// speedup vs baseline: 1.0934x; 1.0705x over previous
#include <cuda_runtime.h>
#include <cuda_fp16.h>
#include <cstdint>

#define B_  64
#define NI  2048
#define DI  16
#define NO  32
#define DO  32
#define CH  16            // i-chunks per (b)
#define IC  (NI / CH)     // 128 i per chunk
#define TI  8             // i per tile
#define NT  (IC / TI)     // 16 tiles per CTA

// u_hat layout: [b][i][o(32)][d(32)] fp16, 268 MB
__device__ __half g_uhat[(size_t)B_ * NI * NO * DO];
__device__ float  g_partA[B_ * CH * NO * DO];
__device__ float  g_partB[B_ * CH * NO * DO];
__device__ float  g_partC[B_ * CH * NO * DO];

// ---------- packed f32x2 helpers ----------
__device__ __forceinline__ unsigned long long splat2(float v) {
    unsigned long long r;
    asm("mov.b64 %0, {%1, %1};" : "=l"(r) : "f"(v));
    return r;
}
__device__ __forceinline__ unsigned long long pack2(float x, float y) {
    unsigned long long r;
    asm("mov.b64 %0, {%1, %2};" : "=l"(r) : "f"(x), "f"(y));
    return r;
}
__device__ __forceinline__ void ffma2(unsigned long long &d,
                                      unsigned long long a, unsigned long long b) {
    asm("fma.rn.f32x2 %0, %1, %2, %0;" : "+l"(d) : "l"(a), "l"(b));
}
__device__ __forceinline__ void add2(unsigned long long &d, unsigned long long a) {
    asm("add.rn.f32x2 %0, %0, %1;" : "+l"(d) : "l"(a));
}
__device__ __forceinline__ float2 unpack2(unsigned long long v) {
    float2 f;
    asm("mov.b64 {%0, %1}, %2;" : "=f"(f.x), "=f"(f.y) : "l"(v));
    return f;
}

// ---------------------------------------------------------------------------
// K1: u_hat[b][i][o][d] = sum_k W[o][i][d][k] * x[b][i][k]   (fp16 out)
// ---------------------------------------------------------------------------
__global__ __launch_bounds__(512, 1)
void k1_uhat(const float* __restrict__ x, const float* __restrict__ W) {
    const int i = blockIdx.x;
    const int t = threadIdx.x;

    __shared__ __align__(16) float xs[DI][B_];
    {
        int idx = t;
        #pragma unroll
        for (int r = 0; r < 2; r++, idx += 512) {
            int b = idx >> 4, k = idx & 15;
            xs[k][b] = x[((size_t)b * NI + i) * DI + k];
        }
    }

    const int o = t >> 4, dp = t & 15;           // d = 2dp, 2dp+1
    const float4* wp = reinterpret_cast<const float4*>(W) +
                       ((((size_t)o * NI + i) * DO + 2 * dp) * DI >> 2);
    float4 qa = wp[0], qb = wp[1], qc = wp[2], qd = wp[3];
    float4 qe = wp[4], qf = wp[5], qg = wp[6], qh = wp[7];

    unsigned long long w0[16], w1[16];
    w0[0]=splat2(qa.x); w0[1]=splat2(qa.y); w0[2]=splat2(qa.z); w0[3]=splat2(qa.w);
    w0[4]=splat2(qb.x); w0[5]=splat2(qb.y); w0[6]=splat2(qb.z); w0[7]=splat2(qb.w);
    w0[8]=splat2(qc.x); w0[9]=splat2(qc.y); w0[10]=splat2(qc.z); w0[11]=splat2(qc.w);
    w0[12]=splat2(qd.x); w0[13]=splat2(qd.y); w0[14]=splat2(qd.z); w0[15]=splat2(qd.w);
    w1[0]=splat2(qe.x); w1[1]=splat2(qe.y); w1[2]=splat2(qe.z); w1[3]=splat2(qe.w);
    w1[4]=splat2(qf.x); w1[5]=splat2(qf.y); w1[6]=splat2(qf.z); w1[7]=splat2(qf.w);
    w1[8]=splat2(qg.x); w1[9]=splat2(qg.y); w1[10]=splat2(qg.z); w1[11]=splat2(qg.w);
    w1[12]=splat2(qh.x); w1[13]=splat2(qh.y); w1[14]=splat2(qh.z); w1[15]=splat2(qh.w);

    __syncthreads();

    __half2* ob = reinterpret_cast<__half2*>(g_uhat) +
                  (size_t)i * 512 + o * 16 + dp;
    const size_t bs2 = (size_t)NI * 512;

    #pragma unroll 1
    for (int bq = 0; bq < 16; bq++) {
        const int b = bq * 4;
        unsigned long long a0p = 0ull, a0q = 0ull;
        unsigned long long a1p = 0ull, a1q = 0ull;
        #pragma unroll
        for (int k = 0; k < 16; k++) {
            ulonglong2 xq = *reinterpret_cast<const ulonglong2*>(&xs[k][b]);
            ffma2(a0p, w0[k], xq.x);
            ffma2(a0q, w0[k], xq.y);
            ffma2(a1p, w1[k], xq.x);
            ffma2(a1q, w1[k], xq.y);
        }
        float2 f0p = unpack2(a0p), f0q = unpack2(a0q);
        float2 f1p = unpack2(a1p), f1q = unpack2(a1q);
        ob[(size_t)(b + 0) * bs2] = __float22half2_rn(make_float2(f0p.x, f1p.x));
        ob[(size_t)(b + 1) * bs2] = __float22half2_rn(make_float2(f0p.y, f1p.y));
        ob[(size_t)(b + 2) * bs2] = __float22half2_rn(make_float2(f0q.x, f1q.x));
        ob[(size_t)(b + 3) * bs2] = __float22half2_rn(make_float2(f0q.y, f1q.y));
    }
}

// ---------------------------------------------------------------------------
// Routing round with cp.async double-buffered smem tiles.
// CTA = (chunk, b), 256 threads. Warp covers 8 o x 4 q (q owns 8 d);
// warps 0-3 handle tile-i 0-3, warps 4-7 handle tile-i 4-7.
// mode 0: c=1/32 -> pA.  mode 1: v(pA) -> pB.  mode 2: v(pA)+v(pB) -> pC.
// ---------------------------------------------------------------------------
__global__ __launch_bounds__(256, 3)
void k_round(int mode) {
    __shared__ __align__(16) uint4 s_tile[2][TI * 128];   // 2 x 16 KB
    __shared__ float s_db[TI][NO];
    __shared__ float s_c[TI][NO];

    const int ch = blockIdx.x, b = blockIdx.y;
    const int t = threadIdx.x;
    const int w = t >> 5, lane = t & 31;
    const int o = ((w & 3) << 3) + (lane >> 2);
    const int q = lane & 3;                 // owns d = 8q .. 8q+7
    const int half = w >> 2;

    const uint4* gbase = reinterpret_cast<const uint4*>(g_uhat) +
                         ((size_t)b * NI + (size_t)ch * IC) * 128;

    // issue tile 0
    {
        const uint4* src = gbase + t;
        unsigned daddr = (unsigned)__cvta_generic_to_shared(&s_tile[0][t]);
        #pragma unroll
        for (int r = 0; r < 4; r++)
            asm volatile("cp.async.cg.shared.global [%0], [%1], 16;"
                :: "r"(daddr + r * 256 * 16), "l"(src + r * 256) : "memory");
        asm volatile("cp.async.commit_group;" ::: "memory");
    }

    // ---- fused vsum prologue (overlaps with tile-0 load)
    unsigned long long vs2[4];
    if (mode >= 1) {
        float vsum[8];
        #pragma unroll
        for (int d = 0; d < 8; d++) vsum[d] = 0.f;
        const float* bufs[2] = { g_partA, g_partB };
        const int nbuf = (mode == 2) ? 2 : 1;
        for (int bi = 0; bi < nbuf; bi++) {
            float s0[8];
            #pragma unroll
            for (int d = 0; d < 8; d++) s0[d] = 0.f;
            const float4* pp = reinterpret_cast<const float4*>(
                bufs[bi] + (size_t)(b * CH) * (NO * DO) + o * DO + q * 8);
            #pragma unroll
            for (int c = 0; c < CH; c++) {
                float4 x0 = pp[c * (NO * DO / 4)];
                float4 x1 = pp[c * (NO * DO / 4) + 1];
                s0[0]+=x0.x; s0[1]+=x0.y; s0[2]+=x0.z; s0[3]+=x0.w;
                s0[4]+=x1.x; s0[5]+=x1.y; s0[6]+=x1.z; s0[7]+=x1.w;
            }
            float nrm = 0.f;
            #pragma unroll
            for (int d = 0; d < 8; d++) nrm += s0[d] * s0[d];
            nrm += __shfl_xor_sync(0xffffffffu, nrm, 1);
            nrm += __shfl_xor_sync(0xffffffffu, nrm, 2);
            float scale = nrm / (1.0f + nrm) * rsqrtf(nrm + 1e-7f);
            #pragma unroll
            for (int d = 0; d < 8; d++) vsum[d] += s0[d] * scale;
        }
        #pragma unroll
        for (int p = 0; p < 4; p++) vs2[p] = pack2(vsum[2*p], vsum[2*p+1]);
    }

    unsigned long long sp2[4] = {0ull, 0ull, 0ull, 0ull};
    const int slot = (w & 3) * 32 + lane;   // == o*4 + q

    #pragma unroll 1
    for (int T = 0; T < NT; T++) {
        // issue tile T+1 (or empty commit for tail) BEFORE waiting on T
        if (T + 1 < NT) {
            const uint4* src = gbase + (size_t)(T + 1) * (TI * 128) + t;
            unsigned daddr = (unsigned)__cvta_generic_to_shared(
                &s_tile[(T + 1) & 1][t]);
            #pragma unroll
            for (int r = 0; r < 4; r++)
                asm volatile("cp.async.cg.shared.global [%0], [%1], 16;"
                    :: "r"(daddr + r * 256 * 16), "l"(src + r * 256) : "memory");
        }
        asm volatile("cp.async.commit_group;" ::: "memory");
        asm volatile("cp.async.wait_group 1;" ::: "memory");
        __syncthreads();

        // consume tile T from smem: 4 i per thread (half selects which 4)
        const uint4* st = s_tile[T & 1];
        uint4 raw[4];
        #pragma unroll
        for (int v = 0; v < 4; v++)
            raw[v] = st[(half * 4 + v) * 128 + slot];

        unsigned long long F2[4][4];
        #pragma unroll
        for (int v = 0; v < 4; v++) {
            const unsigned* ru = reinterpret_cast<const unsigned*>(&raw[v]);
            #pragma unroll
            for (int p = 0; p < 4; p++) {
                float2 f = __half22float2(*reinterpret_cast<const __half2*>(&ru[p]));
                F2[v][p] = pack2(f.x, f.y);
            }
        }

        if (mode >= 1) {
            // phase A: db = vsum . u_hat (reduce over 4 q-lanes)
            #pragma unroll
            for (int v = 0; v < 4; v++) {
                unsigned long long acc = 0ull;
                #pragma unroll
                for (int p = 0; p < 4; p++) ffma2(acc, F2[v][p], vs2[p]);
                float2 a = unpack2(acc);
                float db = a.x + a.y;
                db += __shfl_xor_sync(0xffffffffu, db, 2);
                db += __shfl_xor_sync(0xffffffffu, db, 1);
                if (q == 0) s_db[half * 4 + v][o] = db;
            }
            __syncthreads();
            // phase B: softmax over o (no max subtraction: |logit| <= ~9)
            {
                float e = __expf(s_db[w][lane]);
                float sm = e;
                #pragma unroll
                for (int st2 = 16; st2; st2 >>= 1)
                    sm += __shfl_xor_sync(0xffffffffu, sm, st2);
                s_c[w][lane] = __fdividef(e, sm);
            }
            __syncthreads();
            // phase C
            #pragma unroll
            for (int v = 0; v < 4; v++) {
                unsigned long long c2 = splat2(s_c[half * 4 + v][o]);
                #pragma unroll
                for (int p = 0; p < 4; p++) ffma2(sp2[p], c2, F2[v][p]);
            }
        } else {
            #pragma unroll
            for (int v = 0; v < 4; v++)
                #pragma unroll
                for (int p = 0; p < 4; p++) add2(sp2[p], F2[v][p]);
            __syncthreads();   // protect stage reuse (no phase barriers here)
        }
    }

    float sp[8];
    {
        float2 f0 = unpack2(sp2[0]), f1 = unpack2(sp2[1]);
        float2 f2 = unpack2(sp2[2]), f3 = unpack2(sp2[3]);
        sp[0]=f0.x; sp[1]=f0.y; sp[2]=f1.x; sp[3]=f1.y;
        sp[4]=f2.x; sp[5]=f2.y; sp[6]=f3.x; sp[7]=f3.y;
    }
    if (mode == 0) {
        const float c = 1.0f / (float)NO;
        #pragma unroll
        for (int d = 0; d < 8; d++) sp[d] *= c;
    }

    // combine the two i-half-groups (reuse s_tile[0] as scratch)
    float* s_red = reinterpret_cast<float*>(s_tile);
    #pragma unroll
    for (int d = 0; d < 8; d++)
        s_red[(t & 127) * 8 + d + (half ? 1024 : 0)] = sp[d];
    __syncthreads();
    if (half == 0) {
        float* wb = (mode == 0) ? g_partA : (mode == 1 ? g_partB : g_partC);
        float4* pp = reinterpret_cast<float4*>(
            wb + ((b * CH + ch) * (NO * DO)) + o * DO + q * 8);
        int base = (t & 127) * 8;
        float4 r0, r1;
        r0.x = s_red[base+0] + s_red[base+0+1024];
        r0.y = s_red[base+1] + s_red[base+1+1024];
        r0.z = s_red[base+2] + s_red[base+2+1024];
        r0.w = s_red[base+3] + s_red[base+3+1024];
        r1.x = s_red[base+4] + s_red[base+4+1024];
        r1.y = s_red[base+5] + s_red[base+5+1024];
        r1.z = s_red[base+6] + s_red[base+6+1024];
        r1.w = s_red[base+7] + s_red[base+7+1024];
        pp[0] = r0; pp[1] = r1;
    }
}

// ---------------------------------------------------------------------------
// Final: reduce round-2 partials -> s, squash -> v, write output.
// ---------------------------------------------------------------------------
__global__ __launch_bounds__(1024)
void k_fin(float* __restrict__ out) {
    const int b = blockIdx.x, t = threadIdx.x;
    float s = 0.f;
    #pragma unroll
    for (int c = 0; c < CH; c++)
        s += g_partC[(b * CH + c) * (NO * DO) + t];

    float sq = s * s;
    #pragma unroll
    for (int st = 16; st; st >>= 1)
        sq += __shfl_xor_sync(0xffffffffu, sq, st);

    float scale = sq / (1.0f + sq) * rsqrtf(sq + 1e-7f);
    out[b * (NO * DO) + t] = s * scale;
}

// ---------------------------------------------------------------------------
extern "C" void kernel_launch(void* const* d_in, const int* in_sizes, int n_in,
                              void* d_out, int out_size) {
    const float* x = (const float*)d_in[0];
    const float* W = (const float*)d_in[1];
    if (in_sizes[0] != B_ * NI * DI) {
        x = (const float*)d_in[1];
        W = (const float*)d_in[0];
    }
    float* out = (float*)d_out;

    k1_uhat<<<NI, 512>>>(x, W);

    dim3 rg(CH, B_);
    k_round<<<rg, 256>>>(0);
    k_round<<<rg, 256>>>(1);
    k_round<<<rg, 256>>>(2);
    k_fin<<<B_, NO * DO>>>(out);
}